// round 2
// baseline (speedup 1.0000x reference)
#include <cuda_runtime.h>

// Problem constants
#define L 4
#define B 128
#define T 1024
#define NI 512
#define H 512
#define G 2048          // 4*H
#define BH (B*H)
#define BG (B*G)

#define NBLK 128
#define NTHR 256

// Scratch (device globals: allocation-free rule)
__device__ float g_seq[(size_t)T * BH];    // layer io sequence, (t, b, h), 256 MB
__device__ float g_part[4 * BG];           // splitK partial sums, 4 MB
__device__ unsigned long long g_arrive;
__device__ volatile unsigned long long g_release;

__device__ __forceinline__ void gsync() {
    __syncthreads();
    if (threadIdx.x == 0) {
        __threadfence();
        unsigned long long my = atomicAdd(&g_arrive, 1ULL);
        unsigned long long target = my / NBLK + 1ULL;
        if ((my % NBLK) == (NBLK - 1)) {
            __threadfence();
            g_release = target;
        } else {
            while (g_release < target) { }
        }
        __threadfence();
    }
    __syncthreads();
}

__device__ __forceinline__ float sigmoidf_fast(float x) {
    return 1.0f / (1.0f + __expf(-x));
}

__global__ void __launch_bounds__(NTHR, 1)
lstm_persistent_kernel(const float* __restrict__ x,
                       const float* __restrict__ h0,
                       const float* __restrict__ c0,
                       const float* __restrict__ w_ih,
                       const float* __restrict__ w_hh,
                       const float* __restrict__ b_ih,
                       const float* __restrict__ b_hh,
                       float* __restrict__ out) {
    __shared__ float in_s[128 * 36];   // 128 rows x 32 k, padded stride 36
    __shared__ float w_s[64 * 36];     // 64 cols x 32 k

    const int tid = threadIdx.x;
    const int tx = tid & 15;           // 16 col-groups of 4
    const int ty = tid >> 4;           // 16 row-groups of 8
    const int ntile  = blockIdx.x & 31;   // 32 N-tiles of 64 cols
    const int ksplit = blockIdx.x >> 5;   // 4 K-splits of 256
    const bool is_x = (ksplit < 2);
    const int kb = (ksplit & 1) * 256;    // local k base within source

    // elementwise ownership: 2 (b,h) elements per thread, fixed across steps
    const int e_idx0 = blockIdx.x * 512 + tid * 2;
    const int eb0 = e_idx0 >> 9, eh0 = e_idx0 & 511;
    const int eb1 = (e_idx0 + 1) >> 9, eh1 = (e_idx0 + 1) & 511;

    for (int l = 0; l < L; ++l) {
        const float* wsrc = (is_x ? w_ih : w_hh) + (size_t)l * G * 512;
        const float* h0_l = h0 + (size_t)l * BH;
        const float* c0_l = c0 + (size_t)l * BH;

        // per-layer biases for owned elements (registers)
        float bias0[4], bias1[4];
        #pragma unroll
        for (int gq = 0; gq < 4; ++gq) {
            bias0[gq] = b_ih[(size_t)l * G + gq * H + eh0] + b_hh[(size_t)l * G + gq * H + eh0];
            bias1[gq] = b_ih[(size_t)l * G + gq * H + eh1] + b_hh[(size_t)l * G + gq * H + eh1];
        }
        float creg0 = 0.f, creg1 = 0.f;   // cell state carried in registers

        for (int t = 0; t < T; ++t) {
            // ---------------- GEMM partial: out(b, col) over this block's K range
            const float* src;
            int rs;
            bool src_is_seq;  // true -> must bypass L1 (written cross-SM)
            if (is_x) {
                if (l == 0) { src = x + (size_t)t * NI; rs = T * NI; src_is_seq = false; }
                else        { src = g_seq + (size_t)t * BH; rs = H;  src_is_seq = true;  }
            } else {
                if (t == 0) { src = h0_l; rs = H; src_is_seq = false; }
                else        { src = g_seq + (size_t)(t - 1) * BH; rs = H; src_is_seq = true; }
            }

            float acc[8][4];
            #pragma unroll
            for (int r = 0; r < 8; ++r)
                #pragma unroll
                for (int c = 0; c < 4; ++c) acc[r][c] = 0.f;

            for (int ch = 0; ch < 8; ++ch) {
                const int k0 = kb + ch * 32;
                // stage input tile 128x32
                #pragma unroll
                for (int q = 0; q < 4; ++q) {
                    int idq = tid + q * NTHR;
                    int row = idq >> 3, quad = idq & 7;
                    const float4* gp = (const float4*)(src + (size_t)row * rs + k0 + quad * 4);
                    float4 v;
                    if (src_is_seq) {
                        v = __ldcg(gp);       // L2-only: cross-SM produced data
                    } else {
                        v = __ldg(gp);
                    }
                    *(float4*)&in_s[row * 36 + quad * 4] = v;
                }
                // stage weight tile 64x32
                #pragma unroll
                for (int q = 0; q < 2; ++q) {
                    int idq = tid + q * NTHR;
                    int wrow = idq >> 3, quad = idq & 7;
                    float4 v = __ldg((const float4*)(wsrc + (size_t)(ntile * 64 + wrow) * 512 + k0 + quad * 4));
                    *(float4*)&w_s[wrow * 36 + quad * 4] = v;
                }
                __syncthreads();
                #pragma unroll
                for (int kk = 0; kk < 32; ++kk) {
                    float a[8], wv[4];
                    #pragma unroll
                    for (int r = 0; r < 8; ++r) a[r] = in_s[(ty * 8 + r) * 36 + kk];
                    #pragma unroll
                    for (int c = 0; c < 4; ++c) wv[c] = w_s[(tx * 4 + c) * 36 + kk];
                    #pragma unroll
                    for (int r = 0; r < 8; ++r)
                        #pragma unroll
                        for (int c = 0; c < 4; ++c)
                            acc[r][c] = fmaf(a[r], wv[c], acc[r][c]);
                }
                __syncthreads();
            }
            // write partials (plain STG -> L2)
            {
                float* pp = g_part + (size_t)ksplit * BG + ntile * 64 + tx * 4;
                #pragma unroll
                for (int r = 0; r < 8; ++r) {
                    float4 v = make_float4(acc[r][0], acc[r][1], acc[r][2], acc[r][3]);
                    *(float4*)(pp + (size_t)(ty * 8 + r) * G) = v;
                }
            }
            gsync();

            // ---------------- elementwise: gates -> (c, h) for 2 owned elements
            {
                // element 0
                float vi = bias0[0], vf = bias0[1], vg = bias0[2], vo = bias0[3];
                #pragma unroll
                for (int s = 0; s < 4; ++s) {
                    const float* p = g_part + (size_t)s * BG + (size_t)eb0 * G;
                    vi += __ldcg(p + eh0);
                    vf += __ldcg(p + H + eh0);
                    vg += __ldcg(p + 2 * H + eh0);
                    vo += __ldcg(p + 3 * H + eh0);
                }
                float co = (t == 0) ? c0_l[eb0 * H + eh0] : creg0;
                float cn = fmaf(sigmoidf_fast(vf), co, sigmoidf_fast(vi) * tanhf(vg));
                creg0 = cn;
                g_seq[(size_t)t * BH + eb0 * H + eh0] = sigmoidf_fast(vo) * tanhf(cn);
                if (t == T - 1) out[(size_t)l * BH + eb0 * H + eh0] = cn;
            }
            {
                // element 1
                float vi = bias1[0], vf = bias1[1], vg = bias1[2], vo = bias1[3];
                #pragma unroll
                for (int s = 0; s < 4; ++s) {
                    const float* p = g_part + (size_t)s * BG + (size_t)eb1 * G;
                    vi += __ldcg(p + eh1);
                    vf += __ldcg(p + H + eh1);
                    vg += __ldcg(p + 2 * H + eh1);
                    vo += __ldcg(p + 3 * H + eh1);
                }
                float co = (t == 0) ? c0_l[eb1 * H + eh1] : creg1;
                float cn = fmaf(sigmoidf_fast(vf), co, sigmoidf_fast(vi) * tanhf(vg));
                creg1 = cn;
                g_seq[(size_t)t * BH + eb1 * H + eh1] = sigmoidf_fast(vo) * tanhf(cn);
                if (t == T - 1) out[(size_t)l * BH + eb1 * H + eh1] = cn;
            }
            gsync();   // h(t) visible before GEMM(t+1) / next layer reads
        }
    }
}

extern "C" void kernel_launch(void* const* d_in, const int* in_sizes, int n_in,
                              void* d_out, int out_size) {
    const float* x    = (const float*)d_in[0];
    const float* h0   = (const float*)d_in[1];
    const float* c0   = (const float*)d_in[2];
    const float* w_ih = (const float*)d_in[3];
    const float* w_hh = (const float*)d_in[4];
    const float* b_ih = (const float*)d_in[5];
    const float* b_hh = (const float*)d_in[6];
    float* out = (float*)d_out;

    lstm_persistent_kernel<<<NBLK, NTHR>>>(x, h0, c0, w_ih, w_hh, b_ih, b_hh, out);
}

// round 3
// speedup vs baseline: 1.9577x; 1.9577x over previous
#include <cuda_runtime.h>
#include <cuda_bf16.h>

#define L 4
#define B 128
#define T 1024
#define NI 512
#define H 512
#define G 2048
#define BH (B*H)

#define NBLK 128
#define NTHR 256

// ---- smem layout (bytes): W 64x256 hi/lo (row stride 528), P 128x64 hi/lo (row stride 144)
#define WS_HI 0
#define WS_LO 33792
#define AS_HI 67584
#define AS_LO 86016
#define SMEM_BYTES 104448

// ---- device scratch (allocation-free rule) ----
__device__ unsigned g_x_pack[(size_t)B * T * NI];     // 256 MB: (lo16|hi16) packed bf16
__device__ unsigned g_seq_pack[(size_t)T * BH];       // 128 MB
__device__ unsigned g_h0_pack[(size_t)L * BH];
__device__ float g_part[(size_t)4 * G * B];           // [ksplit][gate][b]
__device__ unsigned long long g_flags[NBLK];

__device__ __forceinline__ unsigned long long ldvol(const unsigned long long* p) {
    unsigned long long v;
    asm volatile("ld.volatile.global.u64 %0, [%1];" : "=l"(v) : "l"(p));
    return v;
}

__device__ __forceinline__ void gbar(unsigned long long ep) {
    __syncthreads();
    __threadfence();
    if (threadIdx.x == 0) atomicExch(&g_flags[blockIdx.x], ep);
    if (threadIdx.x < NBLK) {
        while (ldvol(&g_flags[threadIdx.x]) < ep) { }
    }
    __threadfence();
    __syncthreads();
}

__device__ __forceinline__ unsigned packf(float v) {
    __nv_bfloat16 h = __float2bfloat16(v);
    float hf = __bfloat162float(h);
    __nv_bfloat16 lo = __float2bfloat16(v - hf);
    unsigned short uh = *(unsigned short*)&h;
    unsigned short ul = *(unsigned short*)&lo;
    return ((unsigned)ul << 16) | (unsigned)uh;
}

__device__ __forceinline__ void ldsm4(unsigned r[4], unsigned addr) {
    asm volatile("ldmatrix.sync.aligned.m8n8.x4.shared.b16 {%0,%1,%2,%3}, [%4];"
                 : "=r"(r[0]), "=r"(r[1]), "=r"(r[2]), "=r"(r[3]) : "r"(addr));
}

__device__ __forceinline__ void mma16816(float c[4], const unsigned a[4],
                                         unsigned b0, unsigned b1) {
    asm volatile(
        "mma.sync.aligned.m16n8k16.row.col.f32.bf16.bf16.f32 "
        "{%0,%1,%2,%3}, {%4,%5,%6,%7}, {%8,%9}, {%0,%1,%2,%3};"
        : "+f"(c[0]), "+f"(c[1]), "+f"(c[2]), "+f"(c[3])
        : "r"(a[0]), "r"(a[1]), "r"(a[2]), "r"(a[3]), "r"(b0), "r"(b1));
}

__device__ __forceinline__ float sigf(float x) { return 1.0f / (1.0f + __expf(-x)); }
__device__ __forceinline__ float tanhg(float x) { return 2.0f / (1.0f + __expf(-2.0f * x)) - 1.0f; }

__global__ void __launch_bounds__(NTHR, 1)
lstm_mma_kernel(const float* __restrict__ x,
                const float* __restrict__ h0,
                const float* __restrict__ c0,
                const float* __restrict__ w_ih,
                const float* __restrict__ w_hh,
                const float* __restrict__ b_ih,
                const float* __restrict__ b_hh,
                float* __restrict__ out) {
    extern __shared__ char sm[];
    const unsigned sbase = (unsigned)__cvta_generic_to_shared(sm);

    const int tid = threadIdx.x, bid = blockIdx.x;
    const int lane = tid & 31, wm = tid >> 5;
    const int ntile = bid & 31;          // 64 gate cols
    const int ksplit = bid >> 5;         // 4 K-splits of 256
    const bool is_x = (ksplit < 2);
    const int kb = (ksplit & 1) * 256;   // k base within 512-wide source

    unsigned long long ep = ldvol(&g_flags[bid]);

    // ---------------- prologue: pack x, h0 ----------------
    {
        const size_t gt = (size_t)bid * NTHR + tid, gs = (size_t)NBLK * NTHR;
        const float4* xs = (const float4*)x;
        const size_t nx = (size_t)B * T * NI / 4;
        for (size_t i = gt; i < nx; i += gs) {
            float4 v = __ldg(xs + i);
            uint4 o = make_uint4(packf(v.x), packf(v.y), packf(v.z), packf(v.w));
            ((uint4*)g_x_pack)[i] = o;
        }
        const float4* hs = (const float4*)h0;
        const size_t nh = (size_t)L * BH / 4;
        for (size_t i = gt; i < nh; i += gs) {
            float4 v = __ldg(hs + i);
            uint4 o = make_uint4(packf(v.x), packf(v.y), packf(v.z), packf(v.w));
            ((uint4*)g_h0_pack)[i] = o;
        }
    }
    gbar(++ep);

    // ---------------- per-thread fragment addresses ----------------
    const int mstripe = wm & 3;          // which 16 of 64 gate cols
    const int nhalf = wm >> 2;           // which 64 of 128 batch
    const unsigned wHiA = sbase + WS_HI + (mstripe * 16 + (lane & 15)) * 528 + (lane >> 4) * 16;
    const unsigned wLoA = wHiA + (WS_LO - WS_HI);
    const int prow = nhalf * 64 + (lane & 7) + ((lane >> 4) << 3);
    const unsigned pHiA = sbase + AS_HI + prow * 144 + ((lane >> 3) & 1) * 16;
    const unsigned pLoA = pHiA + (AS_LO - AS_HI);

    // partial store base: [ksplit][gate][b]
    float* const ppart = g_part + ((size_t)ksplit * G + ntile * 64 + mstripe * 16 + (lane >> 2)) * B
                       + nhalf * 64 + (lane & 3) * 2;

    // elementwise ownership: (h, b) and (h+256, b), lanes -> adjacent b
    const int e = bid * NTHR + tid;
    const int eh = e >> 7, ebb = e & 127;

    // P stager indices
    const int srow = tid >> 1, shalf = tid & 1;
    const unsigned stHi = sbase + AS_HI + srow * 144 + shalf * 64;
    const unsigned stLo = stHi + (AS_LO - AS_HI);

    for (int l = 0; l < L; ++l) {
        // ---- stage W slice (hi/lo split), once per layer ----
        {
            const float* wsrc = (is_x ? w_ih : w_hh) + (size_t)l * G * 512;
            for (int it = tid; it < 64 * 64; it += NTHR) {
                int r = it >> 6, c4 = it & 63;
                float4 v = __ldg((const float4*)(wsrc + (size_t)(ntile * 64 + r) * 512 + kb) + c4);
                unsigned ph0 = packf(v.x), ph1 = packf(v.y), ph2 = packf(v.z), ph3 = packf(v.w);
                unsigned hi01 = __byte_perm(ph0, ph1, 0x5410);
                unsigned hi23 = __byte_perm(ph2, ph3, 0x5410);
                unsigned lo01 = __byte_perm(ph0, ph1, 0x7632);
                unsigned lo23 = __byte_perm(ph2, ph3, 0x7632);
                *(uint2*)(sm + WS_HI + r * 528 + c4 * 8) = make_uint2(hi01, hi23);
                *(uint2*)(sm + WS_LO + r * 528 + c4 * 8) = make_uint2(lo01, lo23);
            }
        }
        __syncthreads();

        // per-layer biases and initial cell for owned elements
        float bias0[4], bias1[4];
        #pragma unroll
        for (int q = 0; q < 4; ++q) {
            bias0[q] = __ldg(b_ih + (size_t)l * G + q * H + eh) + __ldg(b_hh + (size_t)l * G + q * H + eh);
            bias1[q] = __ldg(b_ih + (size_t)l * G + q * H + eh + 256) + __ldg(b_hh + (size_t)l * G + q * H + eh + 256);
        }
        float creg0 = __ldg(c0 + (size_t)l * BH + ebb * 512 + eh);
        float creg1 = __ldg(c0 + (size_t)l * BH + ebb * 512 + eh + 256);

        for (int t = 0; t < T; ++t) {
            // ---- source for this block's K range ----
            const unsigned* srcbase;
            size_t rstride;
            if (is_x) {
                if (l == 0) { srcbase = g_x_pack + (size_t)t * NI; rstride = (size_t)T * NI; }
                else        { srcbase = g_seq_pack + (size_t)t * BH; rstride = H; }
            } else {
                if (t == 0) { srcbase = g_h0_pack + (size_t)l * BH; rstride = H; }
                else        { srcbase = g_seq_pack + (size_t)(t - 1) * BH; rstride = H; }
            }

            float acc[8][4];
            #pragma unroll
            for (int j = 0; j < 8; ++j)
                #pragma unroll
                for (int q = 0; q < 4; ++q) acc[j][q] = 0.f;

            #pragma unroll 1
            for (int ch = 0; ch < 4; ++ch) {
                // ---- stage P chunk 128 x 64 (hi/lo) ----
                const unsigned* sp = srcbase + (size_t)srow * rstride + kb + ch * 64 + shalf * 32;
                #pragma unroll
                for (int i = 0; i < 8; ++i) {
                    uint4 p = __ldcg((const uint4*)sp + i);
                    unsigned h01 = __byte_perm(p.x, p.y, 0x5410);
                    unsigned h23 = __byte_perm(p.z, p.w, 0x5410);
                    unsigned l01 = __byte_perm(p.x, p.y, 0x7632);
                    unsigned l23 = __byte_perm(p.z, p.w, 0x7632);
                    unsigned off = i * 8;
                    asm volatile("st.shared.v2.u32 [%0], {%1,%2};" :: "r"(stHi + off), "r"(h01), "r"(h23));
                    asm volatile("st.shared.v2.u32 [%0], {%1,%2};" :: "r"(stLo + off), "r"(l01), "r"(l23));
                }
                __syncthreads();

                #pragma unroll
                for (int ks = 0; ks < 4; ++ks) {
                    unsigned wh[4], wl[4];
                    ldsm4(wh, wHiA + ch * 128 + ks * 32);
                    ldsm4(wl, wLoA + ch * 128 + ks * 32);
                    #pragma unroll
                    for (int jp = 0; jp < 4; ++jp) {
                        unsigned ph[4], pl[4];
                        ldsm4(ph, pHiA + jp * (16 * 144) + ks * 32);
                        ldsm4(pl, pLoA + jp * (16 * 144) + ks * 32);
                        mma16816(acc[2 * jp],     wh, ph[0], ph[1]);
                        mma16816(acc[2 * jp],     wl, ph[0], ph[1]);
                        mma16816(acc[2 * jp],     wh, pl[0], pl[1]);
                        mma16816(acc[2 * jp + 1], wh, ph[2], ph[3]);
                        mma16816(acc[2 * jp + 1], wl, ph[2], ph[3]);
                        mma16816(acc[2 * jp + 1], wh, pl[2], pl[3]);
                    }
                }
                __syncthreads();
            }

            // ---- store partials [gate][b] ----
            #pragma unroll
            for (int j = 0; j < 8; ++j) {
                *(float2*)(ppart + j * 8)           = make_float2(acc[j][0], acc[j][1]);
                *(float2*)(ppart + 8 * B + j * 8)   = make_float2(acc[j][2], acc[j][3]);
            }
            gbar(++ep);

            // ---- elementwise: 2 owned (h,b) elements ----
            {
                float v0[4], v1[4];
                #pragma unroll
                for (int q = 0; q < 4; ++q) { v0[q] = bias0[q]; v1[q] = bias1[q]; }
                #pragma unroll
                for (int s = 0; s < 4; ++s) {
                    const float* p = g_part + (size_t)s * G * B + ebb;
                    #pragma unroll
                    for (int q = 0; q < 4; ++q) {
                        v0[q] += __ldcg(p + (size_t)(q * H + eh) * B);
                        v1[q] += __ldcg(p + (size_t)(q * H + eh + 256) * B);
                    }
                }
                float cn0 = fmaf(sigf(v0[1]), creg0, sigf(v0[0]) * tanhg(v0[2]));
                float cn1 = fmaf(sigf(v1[1]), creg1, sigf(v1[0]) * tanhg(v1[2]));
                creg0 = cn0; creg1 = cn1;
                float hv0 = sigf(v0[3]) * tanhg(cn0);
                float hv1 = sigf(v1[3]) * tanhg(cn1);
                g_seq_pack[(size_t)t * BH + ebb * 512 + eh]       = packf(hv0);
                g_seq_pack[(size_t)t * BH + ebb * 512 + eh + 256] = packf(hv1);
                if (t == T - 1) {
                    out[(size_t)l * BH + ebb * 512 + eh]       = cn0;
                    out[(size_t)l * BH + ebb * 512 + eh + 256] = cn1;
                }
            }
            gbar(++ep);
        }
    }
}

extern "C" void kernel_launch(void* const* d_in, const int* in_sizes, int n_in,
                              void* d_out, int out_size) {
    const float* x    = (const float*)d_in[0];
    const float* h0   = (const float*)d_in[1];
    const float* c0   = (const float*)d_in[2];
    const float* w_ih = (const float*)d_in[3];
    const float* w_hh = (const float*)d_in[4];
    const float* b_ih = (const float*)d_in[5];
    const float* b_hh = (const float*)d_in[6];
    float* out = (float*)d_out;

    cudaFuncSetAttribute(lstm_mma_kernel,
                         cudaFuncAttributeMaxDynamicSharedMemorySize, SMEM_BYTES);
    lstm_mma_kernel<<<NBLK, NTHR, SMEM_BYTES>>>(x, h0, c0, w_ih, w_hh, b_ih, b_hh, out);
}

// round 4
// speedup vs baseline: 2.3380x; 1.1943x over previous
#include <cuda_runtime.h>
#include <cuda_bf16.h>

#define L 4
#define B 128
#define T 1024
#define NI 512
#define H 512
#define G 2048
#define BH (B*H)

#define NBLK 128
#define NTHR 512

// ---- smem layout (bytes) ----
// W: 64 rows x 512 k, hi/lo bf16 planes, row stride 1040B (conflict-free ldmatrix)
#define WS_HI 0
#define WS_LO 66560
// P stage: 2 buffers x (hi plane + lo plane), plane = 128 rows x 144B
#define PS 133120
#define PLANE 18432
#define BUFSTRIDE 36864
// gates tile 64 x 32 f32, stride 33 f32
#define GS 206848
#define SMEM_BYTES 215296

// ---- device scratch (allocation-free rule) ----
__device__ unsigned g_x_pack[(size_t)B * T * NI];   // 256 MB packed (lo16|hi16)
__device__ unsigned g_seq_pack[(size_t)T * BH];     // 256 MB
__device__ unsigned g_h0_pack[(size_t)L * BH];
__device__ float g_gx[(size_t)B * T * G];           // 1 GB: [b][t][gate]
__device__ unsigned long long g_flags[NBLK];

__device__ __forceinline__ unsigned long long ldvol(const unsigned long long* p) {
    unsigned long long v;
    asm volatile("ld.volatile.global.u64 %0, [%1];" : "=l"(v) : "l"(p));
    return v;
}

__device__ __forceinline__ void gbar(unsigned long long ep) {
    __syncthreads();
    __threadfence();
    if (threadIdx.x == 0) atomicExch(&g_flags[blockIdx.x], ep);
    if (threadIdx.x < NBLK) {
        while (ldvol(&g_flags[threadIdx.x]) < ep) { }
    }
    __threadfence();
    __syncthreads();
}

__device__ __forceinline__ unsigned packf(float v) {
    __nv_bfloat16 h = __float2bfloat16(v);
    float hf = __bfloat162float(h);
    __nv_bfloat16 lo = __float2bfloat16(v - hf);
    unsigned short uh = *(unsigned short*)&h;
    unsigned short ul = *(unsigned short*)&lo;
    return ((unsigned)ul << 16) | (unsigned)uh;
}

__device__ __forceinline__ void ldsm4(unsigned r[4], unsigned addr) {
    asm volatile("ldmatrix.sync.aligned.m8n8.x4.shared.b16 {%0,%1,%2,%3}, [%4];"
                 : "=r"(r[0]), "=r"(r[1]), "=r"(r[2]), "=r"(r[3]) : "r"(addr));
}

__device__ __forceinline__ void mma16816(float c[4], const unsigned a[4],
                                         unsigned b0, unsigned b1) {
    asm volatile(
        "mma.sync.aligned.m16n8k16.row.col.f32.bf16.bf16.f32 "
        "{%0,%1,%2,%3}, {%4,%5,%6,%7}, {%8,%9}, {%0,%1,%2,%3};"
        : "+f"(c[0]), "+f"(c[1]), "+f"(c[2]), "+f"(c[3])
        : "r"(a[0]), "r"(a[1]), "r"(a[2]), "r"(a[3]), "r"(b0), "r"(b1));
}

__device__ __forceinline__ float sigf(float x) { return 1.0f / (1.0f + __expf(-x)); }
__device__ __forceinline__ float tanhg(float x) { return 2.0f / (1.0f + __expf(-2.0f * x)) - 1.0f; }

// store one packed uint4 (4 values) as hi/lo bf16 into the stage planes
__device__ __forceinline__ void stage_store(char* bufHi, unsigned off, uint4 p) {
    unsigned h0_ = __byte_perm(p.x, p.y, 0x5410);
    unsigned h1_ = __byte_perm(p.z, p.w, 0x5410);
    unsigned l0_ = __byte_perm(p.x, p.y, 0x7632);
    unsigned l1_ = __byte_perm(p.z, p.w, 0x7632);
    *(uint2*)(bufHi + off) = make_uint2(h0_, h1_);
    *(uint2*)(bufHi + PLANE + off) = make_uint2(l0_, l1_);
}

__global__ void __launch_bounds__(NTHR, 1)
lstm_kernel(const float* __restrict__ x,
            const float* __restrict__ h0,
            const float* __restrict__ c0,
            const float* __restrict__ w_ih,
            const float* __restrict__ w_hh,
            const float* __restrict__ b_ih,
            const float* __restrict__ b_hh,
            float* __restrict__ out) {
    extern __shared__ char sm[];
    const unsigned sbase = (unsigned)__cvta_generic_to_shared(sm);
    float* const gates_s = (float*)(sm + GS);

    const int tid = threadIdx.x, bid = blockIdx.x;
    const int lane = tid & 31, warp = tid >> 5;

    unsigned long long ep = ldvol(&g_flags[bid]);

    // ---------------- prologue: pack x, h0 ----------------
    {
        const size_t gt0 = (size_t)bid * NTHR + tid, gs = (size_t)NBLK * NTHR;
        const float4* xs = (const float4*)x;
        const size_t nx = (size_t)B * T * NI / 4;
        for (size_t i = gt0; i < nx; i += gs) {
            float4 v = __ldg(xs + i);
            ((uint4*)g_x_pack)[i] = make_uint4(packf(v.x), packf(v.y), packf(v.z), packf(v.w));
        }
        const float4* hs = (const float4*)h0;
        const size_t nh = (size_t)L * BH / 4;
        for (size_t i = gt0; i < nh; i += gs) {
            float4 v = __ldg(hs + i);
            ((uint4*)g_h0_pack)[i] = make_uint4(packf(v.x), packf(v.y), packf(v.z), packf(v.w));
        }
    }
    gbar(++ep);

    const int gt = bid & 31;    // gate/h tile (x-phase: 64 gate rows; recurrent: 16 h rows)
    const int grp = bid >> 5;   // batch-group (x-phase: b range; recurrent: 32-b tile)

    const int wg = warp >> 2, wsub = warp & 3;
    // A (W) ldmatrix address: rows wg*16..+16, k-halves by lane>>4
    const unsigned wA = sbase + WS_HI + (unsigned)((wg * 16 + (lane & 15)) * 1040 + (lane >> 4) * 16);
    const unsigned wAlo = wA + (WS_LO - WS_HI);
    // B frag relative addresses
    const unsigned pBx_rel = (unsigned)((wsub * 32 + (lane & 7) + ((lane >> 4) << 3)) * 144
                                        + ((lane >> 3) & 1) * 16);
    const unsigned pBr_rel = (unsigned)((wsub * 8 + (lane & 7)) * 144 + (lane >> 3) * 16);

    // elementwise coords
    const int lh = tid & 15, lb = tid >> 4;
    const int eb = grp * 32 + lb;         // batch (recurrent)
    const int egh = gt * 16 + lh;         // h index (recurrent)

    for (int l = 0; l < L; ++l) {
        // ================= x-phase: gx = W_ih * input_seq =================
        // stage W_ih rows [gt*64, +64)
        for (int it = tid; it < 64 * 128; it += NTHR) {
            int r = it >> 7, c4 = it & 127;
            float4 v = __ldg((const float4*)(w_ih + ((size_t)l * G + gt * 64 + r) * 512) + c4);
            unsigned p0 = packf(v.x), p1 = packf(v.y), p2 = packf(v.z), p3 = packf(v.w);
            *(uint2*)(sm + WS_HI + r * 1040 + c4 * 8) =
                make_uint2(__byte_perm(p0, p1, 0x5410), __byte_perm(p2, p3, 0x5410));
            *(uint2*)(sm + WS_LO + r * 1040 + c4 * 8) =
                make_uint2(__byte_perm(p0, p1, 0x7632), __byte_perm(p2, p3, 0x7632));
        }
        __syncthreads();

        {
            const int srow = tid >> 2, ssg = tid & 3;  // stage: 128 rows x 4 uint4
            for (int m = 0; m < 256; ++m) {
                const int bb = grp * 32 + (m >> 3);
                const int t0 = (m & 7) * 128;

                const unsigned* rowp;
                if (l == 0) rowp = g_x_pack + (((size_t)bb << 10) + (size_t)(t0 + srow)) * 512;
                else        rowp = g_seq_pack + ((size_t)((t0 + srow) * 128 + bb)) * 512;

                float acc[4][4];
                #pragma unroll
                for (int f = 0; f < 4; ++f)
                    #pragma unroll
                    for (int q = 0; q < 4; ++q) acc[f][q] = 0.f;

                uint4 rg[4];
                #pragma unroll
                for (int q = 0; q < 4; ++q)
                    rg[q] = __ldcg((const uint4*)rowp + ssg + 4 * q);

                #pragma unroll 1
                for (int c = 0; c < 8; ++c) {
                    __syncthreads();
                    char* bufHi = sm + PS + (c & 1) * BUFSTRIDE;
                    #pragma unroll
                    for (int q = 0; q < 4; ++q)
                        stage_store(bufHi, srow * 144 + (ssg + 4 * q) * 8, rg[q]);
                    if (c < 7) {
                        #pragma unroll
                        for (int q = 0; q < 4; ++q)
                            rg[q] = __ldcg((const uint4*)rowp + (c + 1) * 16 + ssg + 4 * q);
                    }
                    __syncthreads();

                    const unsigned bufo = sbase + PS + (c & 1) * BUFSTRIDE;
                    #pragma unroll
                    for (int q = 0; q < 4; ++q) {
                        unsigned ah[4], al[4];
                        ldsm4(ah, wA + c * 128 + q * 32);
                        ldsm4(al, wAlo + c * 128 + q * 32);
                        #pragma unroll
                        for (int u = 0; u < 2; ++u) {
                            unsigned bh[4], bl[4];
                            unsigned ba = bufo + pBx_rel + u * 2304 + q * 32;
                            ldsm4(bh, ba);
                            ldsm4(bl, ba + PLANE);
                            mma16816(acc[2 * u],     ah, bh[0], bh[1]);
                            mma16816(acc[2 * u],     al, bh[0], bh[1]);
                            mma16816(acc[2 * u],     ah, bl[0], bl[1]);
                            mma16816(acc[2 * u + 1], ah, bh[2], bh[3]);
                            mma16816(acc[2 * u + 1], al, bh[2], bh[3]);
                            mma16816(acc[2 * u + 1], ah, bl[2], bl[3]);
                        }
                    }
                }

                // store gx tile: [b][t][gate]
                const size_t cb = ((size_t)bb << 10) + (size_t)t0;
                const int gr0 = gt * 64 + wg * 16 + (lane >> 2);
                #pragma unroll
                for (int f = 0; f < 4; ++f) {
                    int u = f >> 1, v2 = f & 1;
                    int tt = wsub * 32 + u * 16 + v2 * 8 + (lane & 3) * 2;
                    float* p = g_gx + (cb + tt) * G + gr0;
                    __stcg(p, acc[f][0]);
                    __stcg(p + G, acc[f][1]);
                    __stcg(p + 8, acc[f][2]);
                    __stcg(p + G + 8, acc[f][3]);
                }
            }
        }
        gbar(++ep);

        // ================= recurrent phase =================
        // stage W_hh: local row r -> global gate row (r>>4)*512 + gt*16 + (r&15)
        for (int it = tid; it < 64 * 128; it += NTHR) {
            int r = it >> 7, c4 = it & 127;
            int grow = (r >> 4) * 512 + gt * 16 + (r & 15);
            float4 v = __ldg((const float4*)(w_hh + ((size_t)l * G + grow) * 512) + c4);
            unsigned p0 = packf(v.x), p1 = packf(v.y), p2 = packf(v.z), p3 = packf(v.w);
            *(uint2*)(sm + WS_HI + r * 1040 + c4 * 8) =
                make_uint2(__byte_perm(p0, p1, 0x5410), __byte_perm(p2, p3, 0x5410));
            *(uint2*)(sm + WS_LO + r * 1040 + c4 * 8) =
                make_uint2(__byte_perm(p0, p1, 0x7632), __byte_perm(p2, p3, 0x7632));
        }
        __syncthreads();

        float bias[4];
        #pragma unroll
        for (int g = 0; g < 4; ++g)
            bias[g] = __ldg(b_ih + (size_t)l * G + g * 512 + egh)
                    + __ldg(b_hh + (size_t)l * G + g * 512 + egh);
        float creg = __ldg(c0 + (size_t)l * BH + (size_t)eb * 512 + egh);
        const float* gx_base = g_gx + ((size_t)eb << 10) * G + egh;

        const int hrow = tid >> 4, hsg = tid & 15;  // stage: 32 rows x 16 uint4

        for (int t = 0; t < T; ++t) {
            const unsigned* rowp;
            if (t == 0) rowp = g_h0_pack + ((size_t)(l * 128 + grp * 32 + hrow)) * 512;
            else        rowp = g_seq_pack + ((size_t)((t - 1) * 128 + grp * 32 + hrow)) * 512;

            // prefetch all 8 chunks (MLP=8)
            uint4 hrg[8];
            #pragma unroll
            for (int c = 0; c < 8; ++c)
                hrg[c] = __ldcg((const uint4*)rowp + c * 16 + hsg);

            float a0[4] = {0.f, 0.f, 0.f, 0.f}, a1[4] = {0.f, 0.f, 0.f, 0.f};

            #pragma unroll 1
            for (int c = 0; c < 8; ++c) {
                __syncthreads();
                stage_store(sm + PS, hrow * 144 + hsg * 8, hrg[c]);
                __syncthreads();
                const unsigned bufo = sbase + PS;
                #pragma unroll
                for (int g2 = 0; g2 < 2; ++g2) {
                    unsigned bh[4], bl[4], ah0[4], ah1[4], al0[4], al1[4];
                    unsigned ba = bufo + pBr_rel + g2 * 64;
                    ldsm4(bh, ba);
                    ldsm4(bl, ba + PLANE);
                    ldsm4(ah0, wA + c * 128 + g2 * 64);
                    ldsm4(ah1, wA + c * 128 + g2 * 64 + 32);
                    ldsm4(al0, wAlo + c * 128 + g2 * 64);
                    ldsm4(al1, wAlo + c * 128 + g2 * 64 + 32);
                    mma16816(a0, ah0, bh[0], bh[1]);
                    mma16816(a1, al0, bh[0], bh[1]);
                    mma16816(a1, ah0, bl[0], bl[1]);
                    mma16816(a0, ah1, bh[2], bh[3]);
                    mma16816(a1, al1, bh[2], bh[3]);
                    mma16816(a1, ah1, bl[2], bl[3]);
                }
            }

            // gates -> smem (local gate row = g*16 + j, stride 33)
            {
                int gr = wg * 16 + (lane >> 2);
                int gc = wsub * 8 + (lane & 3) * 2;
                gates_s[gr * 33 + gc]           = a0[0] + a1[0];
                gates_s[gr * 33 + gc + 1]       = a0[1] + a1[1];
                gates_s[(gr + 8) * 33 + gc]     = a0[2] + a1[2];
                gates_s[(gr + 8) * 33 + gc + 1] = a0[3] + a1[3];
            }
            __syncthreads();

            // elementwise (block-local)
            {
                const float* gxt = gx_base + (size_t)t * G;
                float v0 = bias[0] + gates_s[(0 * 16 + lh) * 33 + lb] + __ldcg(gxt);
                float v1 = bias[1] + gates_s[(1 * 16 + lh) * 33 + lb] + __ldcg(gxt + 512);
                float v2 = bias[2] + gates_s[(2 * 16 + lh) * 33 + lb] + __ldcg(gxt + 1024);
                float v3 = bias[3] + gates_s[(3 * 16 + lh) * 33 + lb] + __ldcg(gxt + 1536);
                float ig = sigf(v0), fg = sigf(v1), gg = tanhg(v2), og = sigf(v3);
                creg = fmaf(fg, creg, ig * gg);
                float hv = og * tanhg(creg);
                g_seq_pack[((size_t)t * 128 + eb) * 512 + egh] = packf(hv);
                if (t == T - 1)
                    out[(size_t)l * BH + (size_t)eb * 512 + egh] = creg;
            }
            gbar(++ep);
        }
    }
}

extern "C" void kernel_launch(void* const* d_in, const int* in_sizes, int n_in,
                              void* d_out, int out_size) {
    const float* x    = (const float*)d_in[0];
    const float* h0   = (const float*)d_in[1];
    const float* c0   = (const float*)d_in[2];
    const float* w_ih = (const float*)d_in[3];
    const float* w_hh = (const float*)d_in[4];
    const float* b_ih = (const float*)d_in[5];
    const float* b_hh = (const float*)d_in[6];
    float* out = (float*)d_out;

    cudaFuncSetAttribute(lstm_kernel,
                         cudaFuncAttributeMaxDynamicSharedMemorySize, SMEM_BYTES);
    lstm_kernel<<<NBLK, NTHR, SMEM_BYTES>>>(x, h0, c0, w_ih, w_hh, b_ih, b_hh, out);
}

// round 5
// speedup vs baseline: 3.1940x; 1.3661x over previous
#include <cuda_runtime.h>
#include <cuda_bf16.h>

#define L 4
#define B 128
#define T 1024
#define NI 512
#define H 512
#define G 2048
#define BH (B*H)

#define NBLK 128
#define NTHR 512

// ---- smem layout (bytes) ----
// W: 64 rows x 512 k, hi/lo bf16 planes, row stride 1040B
#define WS_HI 0
#define WS_LO 66560
// x-phase stage: 2 buffers x (hi+lo planes), plane = 128 rows x 144B
#define PS 133120
#define PLANE 18432
#define BUFSTRIDE 36864
// recurrent stage: 32 rows x 512 k hi/lo planes, row stride 1040B
#define RS 133120
#define RPLANE 33280
// gates tile 64 x 32 f32, stride 33
#define GS 206848
#define SMEM_BYTES 215296

// ---- device scratch ----
__device__ unsigned g_x_pack[(size_t)B * T * NI];
__device__ unsigned g_seq_pack[(size_t)T * BH];
__device__ unsigned g_h0_pack[(size_t)L * BH];
__device__ float g_gx[(size_t)B * T * G];           // [b][t][gate]
__device__ unsigned long long g_flags[NBLK];

__device__ __forceinline__ unsigned long long ldvol(const unsigned long long* p) {
    unsigned long long v;
    asm volatile("ld.volatile.global.u64 %0, [%1];" : "=l"(v) : "l"(p));
    return v;
}

// global barrier (prologue only)
__device__ __forceinline__ void gbar_all(unsigned long long ep) {
    __syncthreads();
    __threadfence();
    if (threadIdx.x == 0) atomicExch(&g_flags[blockIdx.x], ep);
    if (threadIdx.x < NBLK) {
        while (ldvol(&g_flags[threadIdx.x]) < ep) { }
    }
    __threadfence();
    __syncthreads();
}

// group barrier: 32 blocks sharing a batch group
__device__ __forceinline__ void gbar_grp(unsigned long long ep, int grp) {
    __syncthreads();
    __threadfence();
    if (threadIdx.x == 0) atomicExch(&g_flags[blockIdx.x], ep);
    if (threadIdx.x < 32) {
        while (ldvol(&g_flags[grp * 32 + threadIdx.x]) < ep) { }
    }
    __threadfence();
    __syncthreads();
}

__device__ __forceinline__ unsigned packf(float v) {
    __nv_bfloat16 h = __float2bfloat16(v);
    float hf = __bfloat162float(h);
    __nv_bfloat16 lo = __float2bfloat16(v - hf);
    unsigned short uh = *(unsigned short*)&h;
    unsigned short ul = *(unsigned short*)&lo;
    return ((unsigned)ul << 16) | (unsigned)uh;
}

__device__ __forceinline__ void ldsm4(unsigned r[4], unsigned addr) {
    asm volatile("ldmatrix.sync.aligned.m8n8.x4.shared.b16 {%0,%1,%2,%3}, [%4];"
                 : "=r"(r[0]), "=r"(r[1]), "=r"(r[2]), "=r"(r[3]) : "r"(addr));
}

__device__ __forceinline__ void mma16816(float c[4], const unsigned a[4],
                                         unsigned b0, unsigned b1) {
    asm volatile(
        "mma.sync.aligned.m16n8k16.row.col.f32.bf16.bf16.f32 "
        "{%0,%1,%2,%3}, {%4,%5,%6,%7}, {%8,%9}, {%0,%1,%2,%3};"
        : "+f"(c[0]), "+f"(c[1]), "+f"(c[2]), "+f"(c[3])
        : "r"(a[0]), "r"(a[1]), "r"(a[2]), "r"(a[3]), "r"(b0), "r"(b1));
}

__device__ __forceinline__ float sigf(float x) { return 1.0f / (1.0f + __expf(-x)); }
__device__ __forceinline__ float tanhg(float x) { return 2.0f / (1.0f + __expf(-2.0f * x)) - 1.0f; }

__device__ __forceinline__ void stage_store(char* bufHi, unsigned off, uint4 p, int plane) {
    unsigned h0_ = __byte_perm(p.x, p.y, 0x5410);
    unsigned h1_ = __byte_perm(p.z, p.w, 0x5410);
    unsigned l0_ = __byte_perm(p.x, p.y, 0x7632);
    unsigned l1_ = __byte_perm(p.z, p.w, 0x7632);
    *(uint2*)(bufHi + off) = make_uint2(h0_, h1_);
    *(uint2*)(bufHi + plane + off) = make_uint2(l0_, l1_);
}

__global__ void __launch_bounds__(NTHR, 1)
lstm_kernel(const float* __restrict__ x,
            const float* __restrict__ h0,
            const float* __restrict__ c0,
            const float* __restrict__ w_ih,
            const float* __restrict__ w_hh,
            const float* __restrict__ b_ih,
            const float* __restrict__ b_hh,
            float* __restrict__ out) {
    extern __shared__ char sm[];
    const unsigned sbase = (unsigned)__cvta_generic_to_shared(sm);
    float* const gates_s = (float*)(sm + GS);

    const int tid = threadIdx.x, bid = blockIdx.x;
    const int lane = tid & 31, warp = tid >> 5;

    unsigned long long ep = ldvol(&g_flags[bid]);

    // ---------------- prologue: pack x, h0 ----------------
    {
        const size_t gt0 = (size_t)bid * NTHR + tid, gs = (size_t)NBLK * NTHR;
        const float4* xs = (const float4*)x;
        const size_t nx = (size_t)B * T * NI / 4;
        for (size_t i = gt0; i < nx; i += gs) {
            float4 v = __ldg(xs + i);
            ((uint4*)g_x_pack)[i] = make_uint4(packf(v.x), packf(v.y), packf(v.z), packf(v.w));
        }
        const float4* hs = (const float4*)h0;
        const size_t nh = (size_t)L * BH / 4;
        for (size_t i = gt0; i < nh; i += gs) {
            float4 v = __ldg(hs + i);
            ((uint4*)g_h0_pack)[i] = make_uint4(packf(v.x), packf(v.y), packf(v.z), packf(v.w));
        }
    }
    gbar_all(++ep);

    const int gt = bid & 31;    // gate/h tile
    const int grp = bid >> 5;   // batch group (32 batches)

    const int wg = warp >> 2, wsub = warp & 3;
    const unsigned wA = sbase + WS_HI + (unsigned)((wg * 16 + (lane & 15)) * 1040 + (lane >> 4) * 16);
    const unsigned wAlo = wA + (WS_LO - WS_HI);
    const unsigned pBx_rel = (unsigned)((wsub * 32 + (lane & 7) + ((lane >> 4) << 3)) * 144
                                        + ((lane >> 3) & 1) * 16);
    // recurrent B frag: batch rows, stride 1040
    const unsigned pBr = sbase + RS + (unsigned)((wsub * 8 + (lane & 7)) * 1040 + (lane >> 3) * 16);

    const int lh = tid & 15, lb = tid >> 4;
    const int eb = grp * 32 + lb;
    const int egh = gt * 16 + lh;

    for (int l = 0; l < L; ++l) {
        // ================= x-phase: gx = W_ih * input_seq =================
        for (int it = tid; it < 64 * 128; it += NTHR) {
            int r = it >> 7, c4 = it & 127;
            float4 v = __ldg((const float4*)(w_ih + ((size_t)l * G + gt * 64 + r) * 512) + c4);
            unsigned p0 = packf(v.x), p1 = packf(v.y), p2 = packf(v.z), p3 = packf(v.w);
            *(uint2*)(sm + WS_HI + r * 1040 + c4 * 8) =
                make_uint2(__byte_perm(p0, p1, 0x5410), __byte_perm(p2, p3, 0x5410));
            *(uint2*)(sm + WS_LO + r * 1040 + c4 * 8) =
                make_uint2(__byte_perm(p0, p1, 0x7632), __byte_perm(p2, p3, 0x7632));
        }
        __syncthreads();

        {
            const int srow = tid >> 2, ssg = tid & 3;
            for (int m = 0; m < 256; ++m) {
                const int bb = grp * 32 + (m >> 3);
                const int t0 = (m & 7) * 128;

                const unsigned* rowp;
                if (l == 0) rowp = g_x_pack + (((size_t)bb << 10) + (size_t)(t0 + srow)) * 512;
                else        rowp = g_seq_pack + ((size_t)((t0 + srow) * 128 + bb)) * 512;

                float acc[4][4];
                #pragma unroll
                for (int f = 0; f < 4; ++f)
                    #pragma unroll
                    for (int q = 0; q < 4; ++q) acc[f][q] = 0.f;

                uint4 rg[4];
                // chunk 0 -> buf0
                #pragma unroll
                for (int q = 0; q < 4; ++q) rg[q] = __ldcg((const uint4*)rowp + ssg + 4 * q);
                #pragma unroll
                for (int q = 0; q < 4; ++q)
                    stage_store(sm + PS, srow * 144 + (ssg + 4 * q) * 8, rg[q], PLANE);
                // prefetch chunk 1
                #pragma unroll
                for (int q = 0; q < 4; ++q) rg[q] = __ldcg((const uint4*)rowp + 16 + ssg + 4 * q);
                __syncthreads();

                #pragma unroll 1
                for (int c = 0; c < 8; ++c) {
                    // store next chunk into the other buffer (overlaps with MMA below)
                    if (c < 7) {
                        char* bufHi = sm + PS + ((c + 1) & 1) * BUFSTRIDE;
                        #pragma unroll
                        for (int q = 0; q < 4; ++q)
                            stage_store(bufHi, srow * 144 + (ssg + 4 * q) * 8, rg[q], PLANE);
                    }
                    if (c < 6) {
                        #pragma unroll
                        for (int q = 0; q < 4; ++q)
                            rg[q] = __ldcg((const uint4*)rowp + (c + 2) * 16 + ssg + 4 * q);
                    }
                    const unsigned bufo = sbase + PS + (c & 1) * BUFSTRIDE;
                    #pragma unroll
                    for (int q = 0; q < 4; ++q) {
                        unsigned ah[4], al[4];
                        ldsm4(ah, wA + c * 128 + q * 32);
                        ldsm4(al, wAlo + c * 128 + q * 32);
                        #pragma unroll
                        for (int u = 0; u < 2; ++u) {
                            unsigned bh[4], bl[4];
                            unsigned ba = bufo + pBx_rel + u * 2304 + q * 32;
                            ldsm4(bh, ba);
                            ldsm4(bl, ba + PLANE);
                            mma16816(acc[2 * u],     ah, bh[0], bh[1]);
                            mma16816(acc[2 * u],     al, bh[0], bh[1]);
                            mma16816(acc[2 * u],     ah, bl[0], bl[1]);
                            mma16816(acc[2 * u + 1], ah, bh[2], bh[3]);
                            mma16816(acc[2 * u + 1], al, bh[2], bh[3]);
                            mma16816(acc[2 * u + 1], ah, bl[2], bl[3]);
                        }
                    }
                    __syncthreads();
                }

                const size_t cb = ((size_t)bb << 10) + (size_t)t0;
                const int gr0 = gt * 64 + wg * 16 + (lane >> 2);
                #pragma unroll
                for (int f = 0; f < 4; ++f) {
                    int u = f >> 1, v2 = f & 1;
                    int tt = wsub * 32 + u * 16 + v2 * 8 + (lane & 3) * 2;
                    float* p = g_gx + (cb + tt) * G + gr0;
                    __stcg(p, acc[f][0]);
                    __stcg(p + G, acc[f][1]);
                    __stcg(p + 8, acc[f][2]);
                    __stcg(p + G + 8, acc[f][3]);
                }
            }
        }
        gbar_grp(++ep, grp);

        // ================= recurrent phase =================
        for (int it = tid; it < 64 * 128; it += NTHR) {
            int r = it >> 7, c4 = it & 127;
            int grow = (r >> 4) * 512 + gt * 16 + (r & 15);
            float4 v = __ldg((const float4*)(w_hh + ((size_t)l * G + grow) * 512) + c4);
            unsigned p0 = packf(v.x), p1 = packf(v.y), p2 = packf(v.z), p3 = packf(v.w);
            *(uint2*)(sm + WS_HI + r * 1040 + c4 * 8) =
                make_uint2(__byte_perm(p0, p1, 0x5410), __byte_perm(p2, p3, 0x5410));
            *(uint2*)(sm + WS_LO + r * 1040 + c4 * 8) =
                make_uint2(__byte_perm(p0, p1, 0x7632), __byte_perm(p2, p3, 0x7632));
        }
        __syncthreads();

        float bias[4];
        #pragma unroll
        for (int g = 0; g < 4; ++g)
            bias[g] = __ldg(b_ih + (size_t)l * G + g * 512 + egh)
                    + __ldg(b_hh + (size_t)l * G + g * 512 + egh);
        float creg = __ldg(c0 + (size_t)l * BH + (size_t)eb * 512 + egh);
        const float* gx_base = g_gx + ((size_t)eb << 10) * G + egh;

        const int hrow = tid >> 4, hsg = tid & 15;  // 32 rows x 16 uint4 segs

        for (int t = 0; t < T; ++t) {
            // prefetch gx for EW (hides L2/DRAM latency under MMA phase)
            const float* gxt = gx_base + (size_t)t * G;
            float gx0 = __ldcg(gxt);
            float gx1 = __ldcg(gxt + 512);
            float gx2 = __ldcg(gxt + 1024);
            float gx3 = __ldcg(gxt + 1536);

            const unsigned* rowp;
            if (t == 0) rowp = g_h0_pack + ((size_t)(l * 128 + grp * 32 + hrow)) * 512;
            else        rowp = g_seq_pack + ((size_t)((t - 1) * 128 + grp * 32 + hrow)) * 512;

            uint4 hrg[8];
            #pragma unroll
            for (int c = 0; c < 8; ++c)
                hrg[c] = __ldcg((const uint4*)rowp + c * 16 + hsg);

            // stage whole 32x512 h tile (hi/lo), single sync
            #pragma unroll
            for (int c = 0; c < 8; ++c)
                stage_store(sm + RS, hrow * 1040 + (c * 16 + hsg) * 8, hrg[c], RPLANE);
            __syncthreads();

            float a0[4] = {0.f, 0.f, 0.f, 0.f}, a1[4] = {0.f, 0.f, 0.f, 0.f};
            #pragma unroll
            for (int c = 0; c < 8; ++c) {
                #pragma unroll
                for (int g2 = 0; g2 < 2; ++g2) {
                    unsigned bh[4], bl[4], ah0[4], ah1[4], al0[4], al1[4];
                    unsigned ba = pBr + c * 128 + g2 * 64;
                    ldsm4(bh, ba);
                    ldsm4(bl, ba + RPLANE);
                    ldsm4(ah0, wA + c * 128 + g2 * 64);
                    ldsm4(ah1, wA + c * 128 + g2 * 64 + 32);
                    ldsm4(al0, wAlo + c * 128 + g2 * 64);
                    ldsm4(al1, wAlo + c * 128 + g2 * 64 + 32);
                    mma16816(a0, ah0, bh[0], bh[1]);
                    mma16816(a1, al0, bh[0], bh[1]);
                    mma16816(a1, ah0, bl[0], bl[1]);
                    mma16816(a0, ah1, bh[2], bh[3]);
                    mma16816(a1, al1, bh[2], bh[3]);
                    mma16816(a1, ah1, bl[2], bl[3]);
                }
            }

            {
                int gr = wg * 16 + (lane >> 2);
                int gc = wsub * 8 + (lane & 3) * 2;
                gates_s[gr * 33 + gc]           = a0[0] + a1[0];
                gates_s[gr * 33 + gc + 1]       = a0[1] + a1[1];
                gates_s[(gr + 8) * 33 + gc]     = a0[2] + a1[2];
                gates_s[(gr + 8) * 33 + gc + 1] = a0[3] + a1[3];
            }
            __syncthreads();

            {
                float v0 = bias[0] + gates_s[(0 * 16 + lh) * 33 + lb] + gx0;
                float v1 = bias[1] + gates_s[(1 * 16 + lh) * 33 + lb] + gx1;
                float v2 = bias[2] + gates_s[(2 * 16 + lh) * 33 + lb] + gx2;
                float v3 = bias[3] + gates_s[(3 * 16 + lh) * 33 + lb] + gx3;
                float ig = sigf(v0), fg = sigf(v1), gg = tanhg(v2), og = sigf(v3);
                creg = fmaf(fg, creg, ig * gg);
                float hv = og * tanhg(creg);
                g_seq_pack[((size_t)t * 128 + eb) * 512 + egh] = packf(hv);
                if (t == T - 1)
                    out[(size_t)l * BH + (size_t)eb * 512 + egh] = creg;
            }
            gbar_grp(++ep, grp);
        }
    }
}

extern "C" void kernel_launch(void* const* d_in, const int* in_sizes, int n_in,
                              void* d_out, int out_size) {
    const float* x    = (const float*)d_in[0];
    const float* h0   = (const float*)d_in[1];
    const float* c0   = (const float*)d_in[2];
    const float* w_ih = (const float*)d_in[3];
    const float* w_hh = (const float*)d_in[4];
    const float* b_ih = (const float*)d_in[5];
    const float* b_hh = (const float*)d_in[6];
    float* out = (float*)d_out;

    cudaFuncSetAttribute(lstm_kernel,
                         cudaFuncAttributeMaxDynamicSharedMemorySize, SMEM_BYTES);
    lstm_kernel<<<NBLK, NTHR, SMEM_BYTES>>>(x, h0, c0, w_ih, w_hh, b_ih, b_hh, out);
}